// round 7
// baseline (speedup 1.0000x reference)
#include <cuda_runtime.h>
#include <cuda_bf16.h>
#include <float.h>

// BinsChamferLoss, single fused kernel (R7: read-filtered atomics).
// sum over (b,p) of min_t | center(b,p) - target(b,t) |, targets masked to 0 below 0.001.
//
// Encodings (targets >= 0 -> float bits order-isomorphic to u32):
//   maxBelow: enc = bits(t) + 1   (u32 atomicMax; 0 = none)
//   minAbove: enc = ~bits(t)      (u32 atomicMax == min over t; 0 = none)
//
// R7 key change: every atomicMax is guarded by a plain read ("if my candidate
// doesn't beat the currently visible value, skip"). Values are monotonically
// non-decreasing, so a stale read is always <= the true value => skipping is
// safe, and redundant atomics from stale-low reads are merely wasted work.
// This converts ~1.23M smem ATOMS (2 cyc/lane each) into ~cheap LDS + O(ln n)
// successful atomics per slot.

#define MAXB 32
#define P_BINS 256
#define MIN_DEPTH 0.001f
#define LUTN 1024

__device__ unsigned int g_maxBelow[MAXB * P_BINS];   // zero-init = "none"
__device__ unsigned int g_minAbove[MAXB * P_BINS];   // zero-init = "none"
__device__ float        g_batchSum[MAXB];
__device__ unsigned int g_cnt[MAXB];
__device__ unsigned int g_done;

__global__ void __launch_bounds__(P_BINS)
k_fused(const float* __restrict__ bins, const float* __restrict__ depth,
        int M, int B, float* __restrict__ out)
{
    const int b    = blockIdx.y;
    const int tid  = threadIdx.x;
    const int lane = tid & 31;
    const int warp = tid >> 5;

    __shared__ float          sC[P_BINS];
    __shared__ unsigned int   sA[P_BINS];
    __shared__ unsigned int   sS[P_BINS];
    __shared__ unsigned short sLUT[LUTN];
    __shared__ unsigned int   wA[8], wS[8];
    __shared__ float          wsum[8];
    __shared__ int            sFinisher;

    // ---- Phase 1: centers + register bitonic sort (shfl for j<32) ----
    float v;
    {
        const float* bb = bins + b * (P_BINS + 1);
        v = 0.5f * (bb[tid] + bb[tid + 1]);
        sA[tid] = 0u;
        sS[tid] = 0u;
    }

#pragma unroll
    for (int k = 2; k <= P_BINS; k <<= 1) {
#pragma unroll
        for (int j = k >> 1; j >= 1; j >>= 1) {
            bool up = ((tid & k) == 0);
            float other;
            if (j >= 32) {
                __syncthreads();
                sC[tid] = v;
                __syncthreads();
                other = sC[tid ^ j];
            } else {
                other = __shfl_xor_sync(0xffffffffu, v, j);
            }
            bool lower = ((tid & j) == 0);
            v = (lower == up) ? fminf(v, other) : fmaxf(v, other);
        }
    }
    __syncthreads();
    sC[tid] = v;
    __syncthreads();

    // ---- Phase 1b: build LUT hint (plain stores, ranges partition [0,LUTN)) ----
    const float cmin = sC[0];
    const float cmax = sC[P_BINS - 1];
    const float span = cmax - cmin;
    const float invw = (span > 0.0f) ? ((float)LUTN / span) : 0.0f;
    {
        float me = sC[tid];
        int st = min(LUTN, max(0, (int)((me - cmin) * invw)));
        int en;
        if (tid == P_BINS - 1) en = LUTN;
        else {
            float nx = sC[tid + 1];
            en = min(LUTN, max(0, (int)((nx - cmin) * invw)));
        }
        if (tid == 0) st = 0;
        for (int k = st; k < en; ++k) sLUT[k] = (unsigned short)tid;
    }
    __syncthreads();

    // ---- Phase 2: scatter (each thread: one float4 slot, guarded) ----
    {
        const float4* tgt4 = (const float4*)(depth + (long long)b * M);
        const int M4 = M >> 2;                       // M % 4 == 0
        const int i = blockIdx.x * blockDim.x + tid;
        if (i < M4) {
            float4 vv = tgt4[i];
            float vals[4] = {vv.x, vv.y, vv.z, vv.w};
#pragma unroll
            for (int q = 0; q < 4; ++q) {
                float t = vals[q];
                t = (t >= MIN_DEPTH) ? t : 0.0f;
                unsigned int tb = __float_as_uint(t);

                // LUT hint -> exact lower_bound via bidirectional walk
                int k = min(LUTN - 1, max(0, (int)((t - cmin) * invw)));
                int base = (int)sLUT[k];
                while (base > 0      && sC[base - 1] >= t) --base;
                while (base < P_BINS && sC[base]     <  t) ++base;
                // base == lower_bound(sC, t)

                if (base < P_BINS) {
                    unsigned int encA = tb + 1u;
                    if (sA[base] < encA) atomicMax(&sA[base], encA);   // read-filtered
                }

                // upper_bound via tie-walk (ties ~never; stays exact)
                int ub = base;
                while (ub < P_BINS && sC[ub] == t) ++ub;
                if (ub > 0) {
                    unsigned int encS = ~tb;
                    if (sS[ub - 1] < encS) atomicMax(&sS[ub - 1], encS);  // read-filtered
                }
            }
        }
    }
    __syncthreads();

    // ---- Phase 3: flush to global scratch (read-filtered; monotone-safe) ----
    {
        unsigned int a = sA[tid], s = sS[tid];
        if (a && g_maxBelow[b * P_BINS + tid] < a)
            atomicMax(&g_maxBelow[b * P_BINS + tid], a);
        if (s && g_minAbove[b * P_BINS + tid] < s)
            atomicMax(&g_minAbove[b * P_BINS + tid], s);
    }

    // ---- Phase 4: last block of this batch reduces it ----
    __threadfence();
    if (tid == 0) {
        unsigned int old = atomicAdd(&g_cnt[b], 1u);
        sFinisher = (old == (unsigned)(gridDim.x - 1));
    }
    __syncthreads();
    if (!sFinisher) return;
    __threadfence();   // acquire all batch-b flushes

    unsigned int encA = atomicMax(&g_maxBelow[b * P_BINS + tid], 0u);
    unsigned int encS = atomicMax(&g_minAbove[b * P_BINS + tid], 0u);
    g_maxBelow[b * P_BINS + tid] = 0u;     // reset for graph replay
    g_minAbove[b * P_BINS + tid] = 0u;
    if (tid == 0) g_cnt[b] = 0u;

    // prefix-max scan over encA (tid order), shuffle-based
    unsigned int pv = encA;
#pragma unroll
    for (int o = 1; o < 32; o <<= 1) {
        unsigned int n = __shfl_up_sync(0xffffffffu, pv, o);
        if (lane >= o) pv = max(pv, n);
    }
    if (lane == 31) wA[warp] = pv;

    // suffix-max scan over encS, shuffle-based
    unsigned int sv = encS;
#pragma unroll
    for (int o = 1; o < 32; o <<= 1) {
        unsigned int n = __shfl_down_sync(0xffffffffu, sv, o);
        if (lane + o < 32) sv = max(sv, n);
    }
    if (lane == 0) wS[warp] = sv;
    __syncthreads();

    unsigned int offA = 0u, offS = 0u;
    for (int w = 0; w < warp; ++w)     offA = max(offA, wA[w]);
    for (int w = warp + 1; w < 8; ++w) offS = max(offS, wS[w]);
    pv = max(pv, offA);
    sv = max(sv, offS);

    float c   = sC[tid];
    float dLo = pv ? (c - __uint_as_float(pv - 1u)) : FLT_MAX;
    float dHi = sv ? (__uint_as_float(~sv) - c)     : FLT_MAX;
    float d   = fminf(dLo, dHi);

#pragma unroll
    for (int o = 16; o >= 1; o >>= 1) d += __shfl_down_sync(0xffffffffu, d, o);
    if (lane == 0) wsum[warp] = d;
    __syncthreads();

    if (tid == 0) {
        float s = 0.0f;
        for (int w = 0; w < 8; ++w) s += wsum[w];
        g_batchSum[b] = s;

        __threadfence();
        unsigned int old = atomicAdd(&g_done, 1u);
        if (old == (unsigned)(B - 1)) {
            __threadfence();
            float tot = 0.0f;
            for (int i = 0; i < B; ++i) tot += g_batchSum[i];
            out[0] = tot;
            g_done = 0u;
        }
    }
}

extern "C" void kernel_launch(void* const* d_in, const int* in_sizes, int n_in,
                              void* d_out, int out_size)
{
    int bi = 0, di = 1;
    if (n_in >= 2 && in_sizes[0] > in_sizes[1]) { bi = 1; di = 0; }
    const float* bins  = (const float*)d_in[bi];
    const float* depth = (const float*)d_in[di];

    const int B = in_sizes[bi] / (P_BINS + 1);
    const int M = in_sizes[di] / B;

    // One float4 per thread in the scatter phase.
    const int M4 = M >> 2;
    const int splits = (M4 + P_BINS - 1) / P_BINS;   // 75 for 320x240

    dim3 grid(splits, B);
    k_fused<<<grid, P_BINS>>>(bins, depth, M, B, (float*)d_out);
}

// round 8
// speedup vs baseline: 1.0021x; 1.0021x over previous
#include <cuda_runtime.h>
#include <cuda_bf16.h>
#include <float.h>

// BinsChamferLoss, single fused kernel (R8: interleaved slot words + acq_rel, no fences).
// sum over (b,p) of min_t | center(b,p) - target(b,t) |, targets masked to 0 below 0.001.
//
// Slot layout: w[i].lo = maxBelow enc for center i   (enc = bits(t)+1; 0 = none)
//              w[i].hi = minAbove enc for center i-1 (enc = ~bits(t);  0 = none)
// A target with lower_bound(base) updates w[base].lo and w[base].hi -> ONE
// LDS.64 filter read serves both updates. Array has P_BINS+1 words.

#define MAXB 32
#define P_BINS 256
#define MIN_DEPTH 0.001f
#define LUTN 1024
#define NW (P_BINS + 1)

__device__ unsigned long long g_W[MAXB * NW];   // zero-init = "none"
__device__ float              g_batchSum[MAXB];
__device__ unsigned int       g_cnt[MAXB];
__device__ unsigned int       g_done;

__device__ __forceinline__ unsigned int atom_add_acqrel(unsigned int* p, unsigned int v)
{
    unsigned int old;
    asm volatile("atom.acq_rel.gpu.global.add.u32 %0, [%1], %2;"
                 : "=r"(old) : "l"(p), "r"(v) : "memory");
    return old;
}

__global__ void __launch_bounds__(P_BINS)
k_fused(const float* __restrict__ bins, const float* __restrict__ depth,
        int M, int B, float* __restrict__ out)
{
    const int b    = blockIdx.y;
    const int tid  = threadIdx.x;
    const int lane = tid & 31;
    const int warp = tid >> 5;

    __shared__ float              sC[P_BINS];
    __shared__ unsigned long long sW[NW];
    __shared__ unsigned short     sLUT[LUTN];
    __shared__ unsigned int       wA[8], wS[8];
    __shared__ float              wsum[8];
    __shared__ int                sFinisher;

    // ---- Phase 1: centers + register bitonic sort (shfl for j<32) ----
    float v;
    {
        const float* bb = bins + b * (P_BINS + 1);
        v = 0.5f * (bb[tid] + bb[tid + 1]);
        sW[tid] = 0ull;
        if (tid == 0) sW[P_BINS] = 0ull;
    }

#pragma unroll
    for (int k = 2; k <= P_BINS; k <<= 1) {
#pragma unroll
        for (int j = k >> 1; j >= 1; j >>= 1) {
            bool up = ((tid & k) == 0);
            float other;
            if (j >= 32) {
                __syncthreads();
                sC[tid] = v;
                __syncthreads();
                other = sC[tid ^ j];
            } else {
                other = __shfl_xor_sync(0xffffffffu, v, j);
            }
            bool lower = ((tid & j) == 0);
            v = (lower == up) ? fminf(v, other) : fmaxf(v, other);
        }
    }
    __syncthreads();
    sC[tid] = v;
    __syncthreads();

    // ---- Phase 1b: LUT hint (plain stores; ranges partition [0,LUTN)) ----
    const float cmin = sC[0];
    const float cmax = sC[P_BINS - 1];
    const float span = cmax - cmin;
    const float invw = (span > 0.0f) ? ((float)LUTN / span) : 0.0f;
    {
        float me = sC[tid];
        int st = min(LUTN, max(0, (int)((me - cmin) * invw)));
        int en;
        if (tid == P_BINS - 1) en = LUTN;
        else {
            float nx = sC[tid + 1];
            en = min(LUTN, max(0, (int)((nx - cmin) * invw)));
        }
        if (tid == 0) st = 0;
        for (int k = st; k < en; ++k) sLUT[k] = (unsigned short)tid;
    }
    __syncthreads();

    // ---- Phase 2: scatter (one float4 per thread, guarded) ----
    {
        const float4* tgt4 = (const float4*)(depth + (long long)b * M);
        const int M4 = M >> 2;                       // M % 4 == 0
        const int i = blockIdx.x * blockDim.x + tid;
        if (i < M4) {
            float4 vv = tgt4[i];
            float vals[4] = {vv.x, vv.y, vv.z, vv.w};
#pragma unroll
            for (int q = 0; q < 4; ++q) {
                float t = vals[q];
                t = (t >= MIN_DEPTH) ? t : 0.0f;
                unsigned int tb = __float_as_uint(t);

                // LUT hint -> exact lower_bound via bidirectional walk
                int k = min(LUTN - 1, max(0, (int)((t - cmin) * invw)));
                int base = (int)sLUT[k];
                while (base > 0 && sC[base - 1] >= t) --base;
                float cur = 0.0f;
                while (base < P_BINS) {
                    cur = sC[base];
                    if (cur < t) ++base; else break;
                }
                // base == lower_bound; if base < P_BINS, cur == sC[base] >= t

                unsigned long long w = sW[base];      // ONE filter read for both
                unsigned int encA = tb + 1u;
                if (base < P_BINS && (unsigned int)w < encA)
                    atomicMax((unsigned int*)&sW[base], encA);          // lo half

                int ub = base;
                if (base < P_BINS && cur == t) {      // tie ~never; exactness kept
                    ++ub;
                    while (ub < P_BINS && sC[ub] == t) ++ub;
                }
                unsigned int encS = ~tb;
                if (ub > 0) {
                    unsigned int hi = (ub == base) ? (unsigned int)(w >> 32)
                                                   : ((unsigned int*)&sW[ub])[1];
                    if (hi < encS)
                        atomicMax(((unsigned int*)&sW[ub]) + 1, encS);  // hi half
                }
            }
        }
    }
    __syncthreads();

    // ---- Phase 3: flush to global scratch (filtered; monotone-safe) ----
    {
        unsigned long long* gw = &g_W[b * NW];
#pragma unroll
        for (int rep = 0; rep < 2; ++rep) {
            int i = (rep == 0) ? tid : P_BINS;
            if (rep == 1 && tid != 0) break;
            unsigned long long vv = sW[i];
            if (vv) {
                unsigned long long g = gw[i];         // one LDG.64 filter
                unsigned int lo = (unsigned int)vv, hi = (unsigned int)(vv >> 32);
                unsigned int* p = (unsigned int*)&gw[i];
                if (lo > (unsigned int)g)         atomicMax(p, lo);
                if (hi > (unsigned int)(g >> 32)) atomicMax(p + 1, hi);
            }
        }
    }

    // ---- Phase 4: last block of this batch reduces it (acq_rel, no fences) ----
    if (tid == 0) {
        unsigned int old = atom_add_acqrel(&g_cnt[b], 1u);
        sFinisher = (old == (unsigned)(gridDim.x - 1));
    }
    __syncthreads();
    if (!sFinisher) return;

    unsigned long long w0 = g_W[b * NW + tid];
    unsigned long long w1 = g_W[b * NW + tid + 1];
    __syncthreads();                 // all reads done before resets
    g_W[b * NW + tid] = 0ull;        // reset for graph replay
    if (tid == 0) { g_W[b * NW + P_BINS] = 0ull; g_cnt[b] = 0u; }

    unsigned int encA = (unsigned int)w0;          // A[tid]
    unsigned int encS = (unsigned int)(w1 >> 32);  // S[tid]

    // prefix-max scan over encA (tid order), shuffle-based
    unsigned int pv = encA;
#pragma unroll
    for (int o = 1; o < 32; o <<= 1) {
        unsigned int n = __shfl_up_sync(0xffffffffu, pv, o);
        if (lane >= o) pv = max(pv, n);
    }
    if (lane == 31) wA[warp] = pv;

    // suffix-max scan over encS, shuffle-based
    unsigned int sv = encS;
#pragma unroll
    for (int o = 1; o < 32; o <<= 1) {
        unsigned int n = __shfl_down_sync(0xffffffffu, sv, o);
        if (lane + o < 32) sv = max(sv, n);
    }
    if (lane == 0) wS[warp] = sv;
    __syncthreads();

    unsigned int offA = 0u, offS = 0u;
    for (int w = 0; w < warp; ++w)     offA = max(offA, wA[w]);
    for (int w = warp + 1; w < 8; ++w) offS = max(offS, wS[w]);
    pv = max(pv, offA);
    sv = max(sv, offS);

    float c   = sC[tid];
    float dLo = pv ? (c - __uint_as_float(pv - 1u)) : FLT_MAX;
    float dHi = sv ? (__uint_as_float(~sv) - c)     : FLT_MAX;
    float d   = fminf(dLo, dHi);

#pragma unroll
    for (int o = 16; o >= 1; o >>= 1) d += __shfl_down_sync(0xffffffffu, d, o);
    if (lane == 0) wsum[warp] = d;
    __syncthreads();

    if (tid == 0) {
        float s = 0.0f;
        for (int w = 0; w < 8; ++w) s += wsum[w];
        g_batchSum[b] = s;

        unsigned int old = atom_add_acqrel(&g_done, 1u);
        if (old == (unsigned)(B - 1)) {
            float tot = 0.0f;
            for (int i = 0; i < B; ++i) tot += g_batchSum[i];
            out[0] = tot;
            g_done = 0u;   // reset for next replay
        }
    }
}

extern "C" void kernel_launch(void* const* d_in, const int* in_sizes, int n_in,
                              void* d_out, int out_size)
{
    int bi = 0, di = 1;
    if (n_in >= 2 && in_sizes[0] > in_sizes[1]) { bi = 1; di = 0; }
    const float* bins  = (const float*)d_in[bi];
    const float* depth = (const float*)d_in[di];

    const int B = in_sizes[bi] / (P_BINS + 1);
    const int M = in_sizes[di] / B;

    const int M4 = M >> 2;
    const int splits = (M4 + P_BINS - 1) / P_BINS;   // one float4 per thread

    dim3 grid(splits, B);
    k_fused<<<grid, P_BINS>>>(bins, depth, M, B, (float*)d_out);
}

// round 9
// speedup vs baseline: 1.0151x; 1.0129x over previous
#include <cuda_runtime.h>
#include <cuda_bf16.h>
#include <float.h>

// BinsChamferLoss (R9: sort-once prep kernel + one-wave main kernel).
// sum over (b,p) of min_t | center(b,p) - target(b,t) |, targets masked to 0 below 0.001.
//
// k_prep (B blocks): sort centers, build LUT, publish to global.
// k_main (19 x B = 152 blocks ~= one wave): load sorted centers+LUT, scatter
// targets into pred/succ slots, flush, per-batch finisher reduce, final sum.
//
// Slot word layout: w[i].lo = maxBelow enc for center i   (enc = bits(t)+1; 0 = none)
//                   w[i].hi = minAbove enc for center i-1 (enc = ~bits(t);  0 = none)

#define MAXB 32
#define P_BINS 256
#define MIN_DEPTH 0.001f
#define LUTN 1024
#define NW (P_BINS + 1)
#define TPB 512
#define F4T 2            // float4 per thread in k_main

__device__ float              g_centers[MAXB * P_BINS];
__device__ unsigned short     g_lut[MAXB * LUTN];
__device__ float              g_cmin[MAXB];
__device__ float              g_invw[MAXB];
__device__ unsigned long long g_W[MAXB * NW];   // zero-init = "none"
__device__ float              g_batchSum[MAXB];
__device__ unsigned int       g_cnt[MAXB];
__device__ unsigned int       g_done;

__device__ __forceinline__ unsigned int atom_add_acqrel(unsigned int* p, unsigned int v)
{
    unsigned int old;
    asm volatile("atom.acq_rel.gpu.global.add.u32 %0, [%1], %2;"
                 : "=r"(old) : "l"(p), "r"(v) : "memory");
    return old;
}

// ---------------- Kernel 1: sort centers + LUT, once per batch ------------
__global__ void __launch_bounds__(P_BINS)
k_prep(const float* __restrict__ bins)
{
    const int b   = blockIdx.x;
    const int tid = threadIdx.x;

    __shared__ float sC[P_BINS];

    float v;
    {
        const float* bb = bins + b * (P_BINS + 1);
        v = 0.5f * (bb[tid] + bb[tid + 1]);
    }

#pragma unroll
    for (int k = 2; k <= P_BINS; k <<= 1) {
#pragma unroll
        for (int j = k >> 1; j >= 1; j >>= 1) {
            bool up = ((tid & k) == 0);
            float other;
            if (j >= 32) {
                __syncthreads();
                sC[tid] = v;
                __syncthreads();
                other = sC[tid ^ j];
            } else {
                other = __shfl_xor_sync(0xffffffffu, v, j);
            }
            bool lower = ((tid & j) == 0);
            v = (lower == up) ? fminf(v, other) : fmaxf(v, other);
        }
    }
    __syncthreads();
    sC[tid] = v;
    g_centers[b * P_BINS + tid] = v;
    __syncthreads();

    const float cmin = sC[0];
    const float cmax = sC[P_BINS - 1];
    const float span = cmax - cmin;
    const float invw = (span > 0.0f) ? ((float)LUTN / span) : 0.0f;
    if (tid == 0) { g_cmin[b] = cmin; g_invw[b] = invw; }

    {
        float me = sC[tid];
        int st = min(LUTN, max(0, (int)((me - cmin) * invw)));
        int en;
        if (tid == P_BINS - 1) en = LUTN;
        else {
            float nx = sC[tid + 1];
            en = min(LUTN, max(0, (int)((nx - cmin) * invw)));
        }
        if (tid == 0) st = 0;
        for (int k = st; k < en; ++k) g_lut[b * LUTN + k] = (unsigned short)tid;
    }
}

// ---------------- Kernel 2: scatter + reduce, one wave --------------------
__global__ void __launch_bounds__(TPB)
k_main(const float* __restrict__ depth, int M, int B, float* __restrict__ out)
{
    const int b    = blockIdx.y;
    const int tid  = threadIdx.x;
    const int lane = tid & 31;
    const int warp = tid >> 5;

    __shared__ float              sC[P_BINS];
    __shared__ unsigned long long sW[NW];
    __shared__ unsigned int       sLUT[LUTN / 2];   // 1024 ushorts as 512 u32
    __shared__ unsigned int       wA[8], wS[8];
    __shared__ float              wsum[8];
    __shared__ int                sFinisher;

    // ---- Prologue: load published centers + LUT (coalesced, MLP-overlapped) ----
    if (tid < P_BINS)  sC[tid]  = g_centers[b * P_BINS + tid];
    sLUT[tid]                   = ((const unsigned int*)(g_lut + b * LUTN))[tid & (LUTN/2 - 1)];
    if (tid < NW)      sW[tid]  = 0ull;
    const float cmin = g_cmin[b];
    const float invw = g_invw[b];
    __syncthreads();

    const unsigned short* lut16 = (const unsigned short*)sLUT;

    // ---- Scatter: F4T float4 per thread ----
    {
        const float4* tgt4 = (const float4*)(depth + (long long)b * M);
        const int M4 = M >> 2;                     // M % 4 == 0
        const int i0 = blockIdx.x * (TPB * F4T) + tid;
#pragma unroll
        for (int f = 0; f < F4T; ++f) {
            const int i = i0 + f * TPB;
            if (i >= M4) break;
            float4 vv = tgt4[i];
            float vals[4] = {vv.x, vv.y, vv.z, vv.w};
#pragma unroll
            for (int q = 0; q < 4; ++q) {
                float t = vals[q];
                t = (t >= MIN_DEPTH) ? t : 0.0f;
                unsigned int tb = __float_as_uint(t);

                int k = min(LUTN - 1, max(0, (int)((t - cmin) * invw)));
                int base = (int)lut16[k];
                while (base > 0 && sC[base - 1] >= t) --base;
                float cur = 0.0f;
                while (base < P_BINS) {
                    cur = sC[base];
                    if (cur < t) ++base; else break;
                }
                // base == lower_bound(sC, t)

                unsigned long long w = sW[base];
                unsigned int encA = tb + 1u;
                if (base < P_BINS && (unsigned int)w < encA)
                    atomicMax((unsigned int*)&sW[base], encA);

                int ub = base;
                if (base < P_BINS && cur == t) {   // ties ~never; exactness kept
                    ++ub;
                    while (ub < P_BINS && sC[ub] == t) ++ub;
                }
                unsigned int encS = ~tb;
                if (ub > 0) {
                    unsigned int hi = (ub == base) ? (unsigned int)(w >> 32)
                                                   : ((unsigned int*)&sW[ub])[1];
                    if (hi < encS)
                        atomicMax(((unsigned int*)&sW[ub]) + 1, encS);
                }
            }
        }
    }
    __syncthreads();

    // ---- Flush to global scratch (filtered; monotone-safe) ----
    if (tid < NW) {
        unsigned long long vv = sW[tid];
        if (vv) {
            unsigned long long* gw = &g_W[b * NW + tid];
            unsigned long long g = *gw;
            unsigned int lo = (unsigned int)vv, hi = (unsigned int)(vv >> 32);
            unsigned int* p = (unsigned int*)gw;
            if (lo > (unsigned int)g)         atomicMax(p, lo);
            if (hi > (unsigned int)(g >> 32)) atomicMax(p + 1, hi);
        }
    }

    // ---- Last block of this batch reduces it (acq_rel arrive) ----
    if (tid == 0) {
        unsigned int old = atom_add_acqrel(&g_cnt[b], 1u);
        sFinisher = (old == (unsigned)(gridDim.x - 1));
    }
    __syncthreads();
    if (!sFinisher) return;

    unsigned long long w0 = 0ull, w1 = 0ull;
    if (tid < P_BINS) {
        w0 = g_W[b * NW + tid];
        w1 = g_W[b * NW + tid + 1];
    }
    __syncthreads();                               // reads before resets
    if (tid < NW) g_W[b * NW + tid] = 0ull;        // reset for graph replay
    if (tid == 0) g_cnt[b] = 0u;

    unsigned int encA = (unsigned int)w0;          // A[tid]
    unsigned int encS = (unsigned int)(w1 >> 32);  // S[tid]

    // prefix-max / suffix-max scans (warps 0..7 hold the 256 slots)
    unsigned int pv = encA;
    unsigned int sv = encS;
    if (warp < 8) {
#pragma unroll
        for (int o = 1; o < 32; o <<= 1) {
            unsigned int n = __shfl_up_sync(0xffffffffu, pv, o);
            if (lane >= o) pv = max(pv, n);
        }
        if (lane == 31) wA[warp] = pv;
#pragma unroll
        for (int o = 1; o < 32; o <<= 1) {
            unsigned int n = __shfl_down_sync(0xffffffffu, sv, o);
            if (lane + o < 32) sv = max(sv, n);
        }
        if (lane == 0) wS[warp] = sv;
    }
    __syncthreads();

    float d = 0.0f;
    if (warp < 8) {
        unsigned int offA = 0u, offS = 0u;
        for (int w = 0; w < warp; ++w)     offA = max(offA, wA[w]);
        for (int w = warp + 1; w < 8; ++w) offS = max(offS, wS[w]);
        pv = max(pv, offA);
        sv = max(sv, offS);

        float c   = sC[tid];
        float dLo = pv ? (c - __uint_as_float(pv - 1u)) : FLT_MAX;
        float dHi = sv ? (__uint_as_float(~sv) - c)     : FLT_MAX;
        d = fminf(dLo, dHi);

#pragma unroll
        for (int o = 16; o >= 1; o >>= 1) d += __shfl_down_sync(0xffffffffu, d, o);
        if (lane == 0) wsum[warp] = d;
    }
    __syncthreads();

    if (tid == 0) {
        float s = 0.0f;
        for (int w = 0; w < 8; ++w) s += wsum[w];
        g_batchSum[b] = s;

        unsigned int old = atom_add_acqrel(&g_done, 1u);
        if (old == (unsigned)(B - 1)) {
            float tot = 0.0f;
            for (int i = 0; i < B; ++i) tot += g_batchSum[i];
            out[0] = tot;
            g_done = 0u;   // reset for next replay
        }
    }
}

extern "C" void kernel_launch(void* const* d_in, const int* in_sizes, int n_in,
                              void* d_out, int out_size)
{
    int bi = 0, di = 1;
    if (n_in >= 2 && in_sizes[0] > in_sizes[1]) { bi = 1; di = 0; }
    const float* bins  = (const float*)d_in[bi];
    const float* depth = (const float*)d_in[di];

    const int B = in_sizes[bi] / (P_BINS + 1);
    const int M = in_sizes[di] / B;

    const int M4 = M >> 2;
    const int splits = (M4 + TPB * F4T - 1) / (TPB * F4T);   // 19 for 320x240

    k_prep<<<B, P_BINS>>>(bins);
    dim3 grid(splits, B);
    k_main<<<grid, TPB>>>(depth, M, B, (float*)d_out);
}

// round 10
// speedup vs baseline: 1.0173x; 1.0022x over previous
#include <cuda_runtime.h>
#include <cuda_bf16.h>
#include <float.h>

// BinsChamferLoss (R10: prep-once + dense grid + batched hint loads).
// sum over (b,p) of min_t | center(b,p) - target(b,t) |, targets masked to 0 below 0.001.
//
// k_prep (B blocks): sort centers, build LUT, publish to global.
// k_main (75 x B = 600 blocks, 256 thr, 1 float4/thr): load centers+LUT,
// scatter targets into pred/succ slot words, flush, finisher reduce per batch.
//
// Slot word layout: w[i].lo = maxBelow enc for center i   (enc = bits(t)+1; 0 = none)
//                   w[i].hi = minAbove enc for center i-1 (enc = ~bits(t);  0 = none)

#define MAXB 32
#define P_BINS 256
#define MIN_DEPTH 0.001f
#define LUTN 1024
#define NW (P_BINS + 1)
#define TPB 256

__device__ float              g_centers[MAXB * P_BINS];
__device__ unsigned short     g_lut[MAXB * LUTN];
__device__ float              g_cmin[MAXB];
__device__ float              g_invw[MAXB];
__device__ unsigned long long g_W[MAXB * NW];   // zero-init = "none"
__device__ float              g_batchSum[MAXB];
__device__ unsigned int       g_cnt[MAXB];
__device__ unsigned int       g_done;

__device__ __forceinline__ unsigned int atom_add_acqrel(unsigned int* p, unsigned int v)
{
    unsigned int old;
    asm volatile("atom.acq_rel.gpu.global.add.u32 %0, [%1], %2;"
                 : "=r"(old) : "l"(p), "r"(v) : "memory");
    return old;
}

// ---------------- Kernel 1: sort centers + LUT, once per batch ------------
__global__ void __launch_bounds__(P_BINS)
k_prep(const float* __restrict__ bins)
{
    const int b   = blockIdx.x;
    const int tid = threadIdx.x;

    __shared__ float sC[P_BINS];

    float v;
    {
        const float* bb = bins + b * (P_BINS + 1);
        v = 0.5f * (bb[tid] + bb[tid + 1]);
    }

#pragma unroll
    for (int k = 2; k <= P_BINS; k <<= 1) {
#pragma unroll
        for (int j = k >> 1; j >= 1; j >>= 1) {
            bool up = ((tid & k) == 0);
            float other;
            if (j >= 32) {
                __syncthreads();
                sC[tid] = v;
                __syncthreads();
                other = sC[tid ^ j];
            } else {
                other = __shfl_xor_sync(0xffffffffu, v, j);
            }
            bool lower = ((tid & j) == 0);
            v = (lower == up) ? fminf(v, other) : fmaxf(v, other);
        }
    }
    __syncthreads();
    sC[tid] = v;
    g_centers[b * P_BINS + tid] = v;
    __syncthreads();

    const float cmin = sC[0];
    const float cmax = sC[P_BINS - 1];
    const float span = cmax - cmin;
    const float invw = (span > 0.0f) ? ((float)LUTN / span) : 0.0f;
    if (tid == 0) { g_cmin[b] = cmin; g_invw[b] = invw; }

    {
        float me = sC[tid];
        int st = min(LUTN, max(0, (int)((me - cmin) * invw)));
        int en;
        if (tid == P_BINS - 1) en = LUTN;
        else {
            float nx = sC[tid + 1];
            en = min(LUTN, max(0, (int)((nx - cmin) * invw)));
        }
        if (tid == 0) st = 0;
        for (int k = st; k < en; ++k) g_lut[b * LUTN + k] = (unsigned short)tid;
    }
}

// ---------------- Kernel 2: scatter + reduce ------------------------------
__global__ void __launch_bounds__(TPB)
k_main(const float* __restrict__ depth, int M, int B, float* __restrict__ out)
{
    const int b    = blockIdx.y;
    const int tid  = threadIdx.x;
    const int lane = tid & 31;
    const int warp = tid >> 5;

    __shared__ float              sC[P_BINS];
    __shared__ unsigned long long sW[NW];
    __shared__ unsigned int       sLUT[LUTN / 2];
    __shared__ unsigned int       wA[8], wS[8];
    __shared__ float              wsum[8];
    __shared__ int                sFinisher;

    // ---- Prologue: coalesced loads of published tables ----
    sC[tid]       = g_centers[b * P_BINS + tid];
    sLUT[tid]     = ((const unsigned int*)(g_lut + b * LUTN))[tid];
    sLUT[tid+256] = ((const unsigned int*)(g_lut + b * LUTN))[tid + 256];
    sW[tid]       = 0ull;
    if (tid == 0) sW[P_BINS] = 0ull;
    const float cmin = g_cmin[b];
    const float invw = g_invw[b];
    __syncthreads();

    const unsigned short* lut16 = (const unsigned short*)sLUT;

    // ---- Scatter: one float4 per thread; hint loads batched for ILP ----
    {
        const float4* tgt4 = (const float4*)(depth + (long long)b * M);
        const int M4 = M >> 2;                     // M % 4 == 0
        const int i = blockIdx.x * TPB + tid;
        if (i < M4) {
            float4 vv = tgt4[i];
            float t[4] = {vv.x, vv.y, vv.z, vv.w};
            int   base[4];
            unsigned int tb[4];

            // Stage 1: mask + hint index + 4 independent LUT loads
#pragma unroll
            for (int q = 0; q < 4; ++q) {
                t[q] = (t[q] >= MIN_DEPTH) ? t[q] : 0.0f;
                tb[q] = __float_as_uint(t[q]);
                int k = min(LUTN - 1, max(0, (int)((t[q] - cmin) * invw)));
                base[q] = (int)lut16[k];
            }

            // Stage 2: walks + filter + atomics
#pragma unroll
            for (int q = 0; q < 4; ++q) {
                float tq = t[q];
                int bs = base[q];
                while (bs > 0 && sC[bs - 1] >= tq) --bs;
                float cur = 0.0f;
                while (bs < P_BINS) {
                    cur = sC[bs];
                    if (cur < tq) ++bs; else break;
                }
                // bs == lower_bound(sC, tq)

                unsigned long long w = sW[bs];       // one LDS.64 filter read
                unsigned int encA = tb[q] + 1u;
                if (bs < P_BINS && (unsigned int)w < encA)
                    atomicMax((unsigned int*)&sW[bs], encA);

                int ub = bs;
                if (bs < P_BINS && cur == tq) {      // ties ~never; exactness kept
                    ++ub;
                    while (ub < P_BINS && sC[ub] == tq) ++ub;
                }
                unsigned int encS = ~tb[q];
                if (ub > 0) {
                    unsigned int hi = (ub == bs) ? (unsigned int)(w >> 32)
                                                 : ((unsigned int*)&sW[ub])[1];
                    if (hi < encS)
                        atomicMax(((unsigned int*)&sW[ub]) + 1, encS);
                }
            }
        }
    }
    __syncthreads();

    // ---- Flush to global scratch (filtered; monotone-safe) ----
    {
#pragma unroll
        for (int rep = 0; rep < 2; ++rep) {
            int idx = (rep == 0) ? tid : P_BINS;
            if (rep == 1 && tid != 0) break;
            unsigned long long vv = sW[idx];
            if (vv) {
                unsigned long long* gw = &g_W[b * NW + idx];
                unsigned long long g = *gw;
                unsigned int lo = (unsigned int)vv, hi = (unsigned int)(vv >> 32);
                unsigned int* p = (unsigned int*)gw;
                if (lo > (unsigned int)g)         atomicMax(p, lo);
                if (hi > (unsigned int)(g >> 32)) atomicMax(p + 1, hi);
            }
        }
    }

    // ---- Last block of this batch reduces it (acq_rel arrive) ----
    if (tid == 0) {
        unsigned int old = atom_add_acqrel(&g_cnt[b], 1u);
        sFinisher = (old == (unsigned)(gridDim.x - 1));
    }
    __syncthreads();
    if (!sFinisher) return;

    unsigned long long w0 = g_W[b * NW + tid];
    unsigned long long w1 = g_W[b * NW + tid + 1];
    __syncthreads();                               // reads before resets
    g_W[b * NW + tid] = 0ull;                      // reset for graph replay
    if (tid == 0) { g_W[b * NW + P_BINS] = 0ull; g_cnt[b] = 0u; }

    unsigned int encA = (unsigned int)w0;          // A[tid]
    unsigned int encS = (unsigned int)(w1 >> 32);  // S[tid]

    // prefix-max / suffix-max scans, shuffle-based
    unsigned int pv = encA;
#pragma unroll
    for (int o = 1; o < 32; o <<= 1) {
        unsigned int n = __shfl_up_sync(0xffffffffu, pv, o);
        if (lane >= o) pv = max(pv, n);
    }
    if (lane == 31) wA[warp] = pv;

    unsigned int sv = encS;
#pragma unroll
    for (int o = 1; o < 32; o <<= 1) {
        unsigned int n = __shfl_down_sync(0xffffffffu, sv, o);
        if (lane + o < 32) sv = max(sv, n);
    }
    if (lane == 0) wS[warp] = sv;
    __syncthreads();

    unsigned int offA = 0u, offS = 0u;
    for (int w = 0; w < warp; ++w)     offA = max(offA, wA[w]);
    for (int w = warp + 1; w < 8; ++w) offS = max(offS, wS[w]);
    pv = max(pv, offA);
    sv = max(sv, offS);

    float c   = sC[tid];
    float dLo = pv ? (c - __uint_as_float(pv - 1u)) : FLT_MAX;
    float dHi = sv ? (__uint_as_float(~sv) - c)     : FLT_MAX;
    float d   = fminf(dLo, dHi);

#pragma unroll
    for (int o = 16; o >= 1; o >>= 1) d += __shfl_down_sync(0xffffffffu, d, o);
    if (lane == 0) wsum[warp] = d;
    __syncthreads();

    if (tid == 0) {
        float s = 0.0f;
        for (int w = 0; w < 8; ++w) s += wsum[w];
        g_batchSum[b] = s;

        unsigned int old = atom_add_acqrel(&g_done, 1u);
        if (old == (unsigned)(B - 1)) {
            float tot = 0.0f;
            for (int i = 0; i < B; ++i) tot += g_batchSum[i];
            out[0] = tot;
            g_done = 0u;   // reset for next replay
        }
    }
}

extern "C" void kernel_launch(void* const* d_in, const int* in_sizes, int n_in,
                              void* d_out, int out_size)
{
    int bi = 0, di = 1;
    if (n_in >= 2 && in_sizes[0] > in_sizes[1]) { bi = 1; di = 0; }
    const float* bins  = (const float*)d_in[bi];
    const float* depth = (const float*)d_in[di];

    const int B = in_sizes[bi] / (P_BINS + 1);
    const int M = in_sizes[di] / B;

    const int M4 = M >> 2;
    const int splits = (M4 + TPB - 1) / TPB;   // 75 for 320x240: one float4/thread

    k_prep<<<B, P_BINS>>>(bins);
    dim3 grid(splits, B);
    k_main<<<grid, TPB>>>(depth, M, B, (float*)d_out);
}